// round 4
// baseline (speedup 1.0000x reference)
#include <cuda_runtime.h>
#include <cuda_bf16.h>
#include <cstdint>

// Problem constants (fixed shapes per reference)
#define NN 50000      // num nodes
#define EE 800000     // num edges
#define CC 64         // channels (in == out)

// Use vector red.global.add.v4.f32 (PTX ISA 8.1+, sm_90+). Set to 0 to fall
// back to 4x scalar atomicAdd.
#define USE_RED_V4 1

// ---------------- scratch (no allocations allowed) ----------------
// __align__(256): these are reinterpreted as float4 / accessed with 128-bit
// ops; device globals otherwise only guarantee element-type alignment.
__device__ __align__(256) int   g_deg[NN];
__device__ __align__(256) float g_dis[NN];
__device__ __align__(256) float g_agg[NN * CC];     // 12.8 MB
__device__ int   g_is64;             // 1 if edge_index is int64, 0 if int32

// ---------------- kernel 1: zero scratch + detect index dtype ----------------
__global__ void k_zero_detect(const void* __restrict__ edges, int E) {
    int64_t i = (int64_t)blockIdx.x * blockDim.x + threadIdx.x;
    int64_t stride = (int64_t)gridDim.x * blockDim.x;
    float4* agg4 = reinterpret_cast<float4*>(g_agg);
    const int64_t n_agg4 = (int64_t)NN * (CC / 4);     // 800000 float4
    for (int64_t k = i; k < n_agg4; k += stride)
        agg4[k] = make_float4(0.f, 0.f, 0.f, 0.f);
    for (int64_t k = i; k < NN; k += stride)
        g_deg[k] = 0;

    if (blockIdx.x == 0 && threadIdx.x == 0) {
        // If edge_index is int64 with nonneg values < 2^31, every odd 32-bit
        // word is zero. If int32 (random in [0, 50000)), odd words are real
        // index values and are ~never all zero over 128 samples.
        const unsigned* w = reinterpret_cast<const unsigned*>(edges);
        int64_t nw = (int64_t)2 * E;       // words available under int32 view
        int all0 = 1;
        for (int64_t k = 1; k < 256 && k < nw; k += 2) {
            if (w[k] != 0u) { all0 = 0; break; }
        }
        g_is64 = all0;
    }
}

__device__ __forceinline__ int load_idx(const void* edges, int64_t pos, int is64) {
    if (is64) return (int)reinterpret_cast<const long long*>(edges)[pos];
    return reinterpret_cast<const int*>(edges)[pos];
}

// ---------------- kernel 2: degree count ----------------
__global__ void k_degree(const void* __restrict__ edges, int E) {
    int is64 = g_is64;
    int64_t i = (int64_t)blockIdx.x * blockDim.x + threadIdx.x;
    if (i >= E) return;
    int tgt = load_idx(edges, (int64_t)E + i, is64);
    atomicAdd(&g_deg[tgt], 1);
}

// ---------------- kernel 3: deg_inv_sqrt ----------------
__global__ void k_norm(int n) {
    int i = blockIdx.x * blockDim.x + threadIdx.x;
    if (i >= n) return;
    float d = (float)g_deg[i];
    g_dis[i] = rsqrtf(fmaxf(d, 1.0f));
}

// ---------------- kernel 4: gather + scale + scatter-add ----------------
// 16 lanes per edge, one float4 each. Leader lane loads indices + norm, shfl-bcast.
__global__ __launch_bounds__(256) void k_scatter(const float* __restrict__ x,
                                                 const void* __restrict__ edges,
                                                 int E) {
    int is64 = g_is64;
    int tid  = threadIdx.x;
    int lane = tid & 31;
    int q    = lane & 15;                 // float4 slot within row
    int64_t e = ((int64_t)blockIdx.x * blockDim.x + tid) >> 4;
    if (e >= E) return;

    int src = 0, tgt = 0;
    float norm = 0.f;
    if (q == 0) {
        src  = load_idx(edges, e, is64);
        tgt  = load_idx(edges, (int64_t)E + e, is64);
        norm = g_dis[src] * g_dis[tgt];
    }
    int leader = lane & 16;               // lane 0 or 16 within this warp half
    src  = __shfl_sync(0xffffffffu, src,  leader);
    tgt  = __shfl_sync(0xffffffffu, tgt,  leader);
    norm = __shfl_sync(0xffffffffu, norm, leader);

    const float4* x4 = reinterpret_cast<const float4*>(x);
    float4 xv = __ldg(&x4[(int64_t)src * 16 + q]);
    float4 m  = make_float4(xv.x * norm, xv.y * norm, xv.z * norm, xv.w * norm);

    float* dst = g_agg + ((int64_t)tgt * CC + q * 4);
#if USE_RED_V4
    asm volatile("red.global.add.v4.f32 [%0], {%1, %2, %3, %4};"
                 :: "l"(dst), "f"(m.x), "f"(m.y), "f"(m.z), "f"(m.w)
                 : "memory");
#else
    atomicAdd(dst + 0, m.x);
    atomicAdd(dst + 1, m.y);
    atomicAdd(dst + 2, m.z);
    atomicAdd(dst + 3, m.w);
#endif
}

// ---------------- kernel 5: out = relu(agg @ W^T + b) ----------------
// One thread per node; W (64x64) + b in shared. LDS are warp-uniform -> broadcast.
__global__ __launch_bounds__(256) void k_gemm(const float* __restrict__ W,
                                              const float* __restrict__ b,
                                              float* __restrict__ out, int n) {
    __shared__ float Ws[CC * CC];
    __shared__ float bs[CC];
    for (int i = threadIdx.x; i < CC * CC; i += blockDim.x) Ws[i] = W[i];
    if (threadIdx.x < CC) bs[threadIdx.x] = b[threadIdx.x];
    __syncthreads();

    int node = blockIdx.x * blockDim.x + threadIdx.x;
    if (node >= n) return;

    float4 a[16];
    const float4* arow = reinterpret_cast<const float4*>(g_agg + (int64_t)node * CC);
#pragma unroll
    for (int i = 0; i < 16; i++) a[i] = arow[i];

    float4* orow = reinterpret_cast<float4*>(out + (int64_t)node * CC);
    const float4* Ws4 = reinterpret_cast<const float4*>(Ws);

#pragma unroll
    for (int o = 0; o < CC; o += 4) {
        float acc0 = bs[o + 0], acc1 = bs[o + 1], acc2 = bs[o + 2], acc3 = bs[o + 3];
#pragma unroll
        for (int c = 0; c < 16; c++) {
            float4 av = a[c];
            float4 w0 = Ws4[(o + 0) * 16 + c];
            float4 w1 = Ws4[(o + 1) * 16 + c];
            float4 w2 = Ws4[(o + 2) * 16 + c];
            float4 w3 = Ws4[(o + 3) * 16 + c];
            acc0 += av.x * w0.x + av.y * w0.y + av.z * w0.z + av.w * w0.w;
            acc1 += av.x * w1.x + av.y * w1.y + av.z * w1.z + av.w * w1.w;
            acc2 += av.x * w2.x + av.y * w2.y + av.z * w2.z + av.w * w2.w;
            acc3 += av.x * w3.x + av.y * w3.y + av.z * w3.z + av.w * w3.w;
        }
        float4 r;
        r.x = fmaxf(acc0, 0.f);
        r.y = fmaxf(acc1, 0.f);
        r.z = fmaxf(acc2, 0.f);
        r.w = fmaxf(acc3, 0.f);
        orow[o >> 2] = r;
    }
}

// ---------------- launch ----------------
extern "C" void kernel_launch(void* const* d_in, const int* in_sizes, int n_in,
                              void* d_out, int out_size) {
    const float* x     = (const float*)d_in[0];
    const void*  edges = d_in[1];                 // int32 or int64, runtime-detected
    const float* W     = (const float*)d_in[2];
    const float* b     = (const float*)d_in[3];
    float* out = (float*)d_out;

    const int n = in_sizes[0] / CC;               // 50000
    const int E = in_sizes[1] / 2;                // 800000

    // 1) zero agg/deg + detect edge dtype
    k_zero_detect<<<3125, 256>>>(edges, E);
    // 2) degree count
    k_degree<<<(E + 255) / 256, 256>>>(edges, E);
    // 3) normalization factors
    k_norm<<<(n + 255) / 256, 256>>>(n);
    // 4) gather + scale + scatter-add (16 lanes/edge)
    {
        int64_t threads = (int64_t)E * 16;
        int blocks = (int)((threads + 255) / 256);
        k_scatter<<<blocks, 256>>>(x, edges, E);
    }
    // 5) fused linear + bias + relu
    k_gemm<<<(n + 255) / 256, 256>>>(W, b, out, n);
}